// round 1
// baseline (speedup 1.0000x reference)
#include <cuda_runtime.h>

#define EMBED   768
#define THREE_E 2304
#define HEADS   12
#define HDIM    64
#define SEQ     1024
#define BATCH   8
#define TOKENS  (BATCH*SEQ)

// QKV scratch: [8192 tokens][2304] fp32 (q | k | v, each 768 = 12 heads * 64)
__device__ float g_qkv[(size_t)TOKENS * THREE_E];

// ---------- packed f32x2 helpers (sm_100+) ----------
__device__ __forceinline__ unsigned long long pk2(float lo, float hi){
    unsigned long long r;
    asm("mov.b64 %0, {%1, %2};" : "=l"(r) : "f"(lo), "f"(hi));
    return r;
}
__device__ __forceinline__ float2 up2(unsigned long long v){
    float2 r;
    asm("mov.b64 {%0, %1}, %2;" : "=f"(r.x), "=f"(r.y) : "l"(v));
    return r;
}
__device__ __forceinline__ void fma2(unsigned long long &d, unsigned long long a, unsigned long long b){
    asm("fma.rn.f32x2 %0, %1, %2, %0;" : "+l"(d) : "l"(a), "l"(b));
}

// ============================================================
// Kernel 1: QKV GEMM  C[8192,2304] = X[8192,768] * W[2304,768]^T + bias
// 128x128 tile, BK=16, 256 threads, 8x8 microtile, f32x2-packed FMA.
// ============================================================
__global__ __launch_bounds__(256, 2)
void qkv_gemm(const float* __restrict__ X, const float* __restrict__ W,
              const float* __restrict__ bias){
    __shared__ float As[16][128];   // As[k][m]
    __shared__ float Bs[16][128];   // Bs[k][n]

    const int tid = threadIdx.x;
    const int bm = blockIdx.y * 128;
    const int bn = blockIdx.x * 128;
    const int tx = tid & 15;        // 16 col-groups of 8
    const int ty = tid >> 4;        // 16 row-groups of 8
    const int lr = tid >> 2;        // 0..63 loader row
    const int lc = (tid & 3) << 2;  // 0,4,8,12 loader k-chunk

    unsigned long long acc[8][4];
    #pragma unroll
    for (int i = 0; i < 8; i++)
        #pragma unroll
        for (int j = 0; j < 4; j++) acc[i][j] = 0ull;

    const float* Ap0 = X + (size_t)(bm + lr)      * EMBED + lc;
    const float* Ap1 = X + (size_t)(bm + lr + 64) * EMBED + lc;
    const float* Bp0 = W + (size_t)(bn + lr)      * EMBED + lc;
    const float* Bp1 = W + (size_t)(bn + lr + 64) * EMBED + lc;

    float4 pa0 = *(const float4*)Ap0;
    float4 pa1 = *(const float4*)Ap1;
    float4 pb0 = *(const float4*)Bp0;
    float4 pb1 = *(const float4*)Bp1;

    const int NKT = EMBED / 16;  // 48
    for (int kt = 0; kt < NKT; kt++){
        __syncthreads();
        {
            float a0[4] = {pa0.x, pa0.y, pa0.z, pa0.w};
            float a1[4] = {pa1.x, pa1.y, pa1.z, pa1.w};
            float b0[4] = {pb0.x, pb0.y, pb0.z, pb0.w};
            float b1[4] = {pb1.x, pb1.y, pb1.z, pb1.w};
            #pragma unroll
            for (int i = 0; i < 4; i++){
                As[lc + i][lr]      = a0[i];
                As[lc + i][lr + 64] = a1[i];
                Bs[lc + i][lr]      = b0[i];
                Bs[lc + i][lr + 64] = b1[i];
            }
        }
        __syncthreads();
        if (kt + 1 < NKT){
            pa0 = *(const float4*)(Ap0 + (kt + 1) * 16);
            pa1 = *(const float4*)(Ap1 + (kt + 1) * 16);
            pb0 = *(const float4*)(Bp0 + (kt + 1) * 16);
            pb1 = *(const float4*)(Bp1 + (kt + 1) * 16);
        }
        #pragma unroll
        for (int kk = 0; kk < 16; kk++){
            float4 a0 = *(const float4*)&As[kk][ty * 8];
            float4 a1 = *(const float4*)&As[kk][ty * 8 + 4];
            ulonglong2 b0 = *(const ulonglong2*)&Bs[kk][tx * 8];
            ulonglong2 b1 = *(const ulonglong2*)&Bs[kk][tx * 8 + 4];
            float av[8] = {a0.x, a0.y, a0.z, a0.w, a1.x, a1.y, a1.z, a1.w};
            #pragma unroll
            for (int i = 0; i < 8; i++){
                unsigned long long aa = pk2(av[i], av[i]);
                fma2(acc[i][0], aa, b0.x);
                fma2(acc[i][1], aa, b0.y);
                fma2(acc[i][2], aa, b1.x);
                fma2(acc[i][3], aa, b1.y);
            }
        }
    }

    float4 bs0 = *(const float4*)&bias[bn + tx * 8];
    float4 bs1 = *(const float4*)&bias[bn + tx * 8 + 4];
    #pragma unroll
    for (int i = 0; i < 8; i++){
        float2 c0 = up2(acc[i][0]), c1 = up2(acc[i][1]);
        float2 c2 = up2(acc[i][2]), c3 = up2(acc[i][3]);
        float4 o0 = make_float4(c0.x + bs0.x, c0.y + bs0.y, c1.x + bs0.z, c1.y + bs0.w);
        float4 o1 = make_float4(c2.x + bs1.x, c2.y + bs1.y, c3.x + bs1.z, c3.y + bs1.w);
        float* cp = g_qkv + (size_t)(bm + ty * 8 + i) * THREE_E + bn + tx * 8;
        *(float4*)cp       = o0;
        *(float4*)(cp + 4) = o1;
    }
}

// ============================================================
// Kernel 2: fused attention. One block = (b, h, 32 Q rows).
// S[32][1024] strip in SMEM (exact 2-pass softmax), K/V streamed in
// 64x64 tiles with XOR chunk swizzle. floor(S/8) applied exactly.
// ============================================================
#define ROWS_PB   32
#define SS_STRIDE 1032   // 1024 + 8 pad (bank spread for broadcast reads)

__global__ __launch_bounds__(256, 1)
void attn_kernel(float* __restrict__ out){
    extern __shared__ float sm[];
    float* Ss   = sm;                       // 32 * 1032
    float* Qs   = sm + 32 * SS_STRIDE;      // 32 * 64 (swizzled)
    float* KVs  = Qs + 32 * 64;             // 64 * 64 (swizzled)
    float* rinv = KVs + 64 * 64;            // 32

    const int tid  = threadIdx.x;
    const int bh   = blockIdx.x >> 5;             // 0..95 = b*12+h
    const int row0 = (blockIdx.x & 31) * ROWS_PB; // Q row offset
    const int b = bh / HEADS;
    const int h = bh % HEADS;

    const float* qbase = g_qkv + (size_t)(b * SEQ) * THREE_E + h * HDIM;
    const float* kbase = qbase + EMBED;
    const float* vbase = qbase + 2 * EMBED;

    // ---- load Q block (32x64), swizzled 16B chunks: phys chunk = c ^ (r&15)
    #pragma unroll
    for (int it = 0; it < 2; it++){
        int idx = it * 256 + tid;
        int c = idx & 15, r = idx >> 4;
        float4 v = *(const float4*)(qbase + (size_t)(row0 + r) * THREE_E + c * 4);
        *(float4*)&Qs[r * 64 + ((c ^ (r & 15)) << 2)] = v;
    }

    // ---- pass 1: S = floor(Q K^T / 8) into Ss
    const int ty2 = tid >> 4;     // 0..15 -> rows 2*ty2, 2*ty2+1
    const int tx4 = tid & 15;     // 0..15 -> cols tx4*4 .. +3
    const int r0 = ty2 * 2, r1 = r0 + 1;
    const int c0 = tx4 * 4;

    for (int kt = 0; kt < SEQ / 64; kt++){
        __syncthreads();
        #pragma unroll
        for (int it = 0; it < 4; it++){
            int idx = it * 256 + tid;
            int c = idx & 15, r = idx >> 4;
            float4 v = *(const float4*)(kbase + (size_t)(kt * 64 + r) * THREE_E + c * 4);
            *(float4*)&KVs[r * 64 + ((c ^ (r & 15)) << 2)] = v;
        }
        __syncthreads();

        unsigned long long s0[4], s1[4];
        #pragma unroll
        for (int j = 0; j < 4; j++){ s0[j] = 0ull; s1[j] = 0ull; }

        #pragma unroll
        for (int cd = 0; cd < 16; cd++){
            ulonglong2 q0 = *(const ulonglong2*)&Qs[r0 * 64 + ((cd ^ (r0 & 15)) << 2)];
            ulonglong2 q1 = *(const ulonglong2*)&Qs[r1 * 64 + ((cd ^ (r1 & 15)) << 2)];
            #pragma unroll
            for (int j = 0; j < 4; j++){
                ulonglong2 kv = *(const ulonglong2*)&KVs[(c0 + j) * 64 + ((cd ^ ((c0 + j) & 15)) << 2)];
                fma2(s0[j], q0.x, kv.x); fma2(s0[j], q0.y, kv.y);
                fma2(s1[j], q1.x, kv.x); fma2(s1[j], q1.y, kv.y);
            }
        }
        float4 w0, w1; float2 t;
        t = up2(s0[0]); w0.x = floorf((t.x + t.y) * 0.125f);
        t = up2(s0[1]); w0.y = floorf((t.x + t.y) * 0.125f);
        t = up2(s0[2]); w0.z = floorf((t.x + t.y) * 0.125f);
        t = up2(s0[3]); w0.w = floorf((t.x + t.y) * 0.125f);
        t = up2(s1[0]); w1.x = floorf((t.x + t.y) * 0.125f);
        t = up2(s1[1]); w1.y = floorf((t.x + t.y) * 0.125f);
        t = up2(s1[2]); w1.z = floorf((t.x + t.y) * 0.125f);
        t = up2(s1[3]); w1.w = floorf((t.x + t.y) * 0.125f);
        *(float4*)&Ss[r0 * SS_STRIDE + kt * 64 + c0] = w0;
        *(float4*)&Ss[r1 * SS_STRIDE + kt * 64 + c0] = w1;
    }
    __syncthreads();

    // ---- softmax (unnormalized exp in-place; 1/sum stashed in rinv)
    {
        const int w = tid >> 5, lane = tid & 31;
        #pragma unroll
        for (int rr = 0; rr < 4; rr++){
            int r = w * 4 + rr;
            float* row = Ss + r * SS_STRIDE;
            float mx = -1e30f;
            #pragma unroll 8
            for (int i = lane; i < SEQ; i += 32) mx = fmaxf(mx, row[i]);
            #pragma unroll
            for (int o = 16; o > 0; o >>= 1) mx = fmaxf(mx, __shfl_xor_sync(0xffffffffu, mx, o));
            float sum = 0.f;
            #pragma unroll 8
            for (int i = lane; i < SEQ; i += 32){
                float e = __expf(row[i] - mx);
                row[i] = e;
                sum += e;
            }
            #pragma unroll
            for (int o = 16; o > 0; o >>= 1) sum += __shfl_xor_sync(0xffffffffu, sum, o);
            if (lane == 0) rinv[r] = 1.0f / sum;
        }
    }

    // ---- pass 2: O = (E @ V) * (1/sum)
    const int oy = tid >> 3;  // 0..31 Q row
    const int ox = tid & 7;   // 0..7  -> D cols ox*8 .. +7
    unsigned long long o[4] = {0ull, 0ull, 0ull, 0ull};

    for (int kt = 0; kt < SEQ / 64; kt++){
        __syncthreads();
        #pragma unroll
        for (int it = 0; it < 4; it++){
            int idx = it * 256 + tid;
            int c = idx & 15, r = idx >> 4;
            float4 v = *(const float4*)(vbase + (size_t)(kt * 64 + r) * THREE_E + c * 4);
            *(float4*)&KVs[r * 64 + ((c ^ (r & 15)) << 2)] = v;
        }
        __syncthreads();
        const float* erow = Ss + oy * SS_STRIDE + kt * 64;
        #pragma unroll 8
        for (int m = 0; m < 64; m++){
            unsigned long long ee = pk2(erow[m], erow[m]);
            ulonglong2 va = *(const ulonglong2*)&KVs[m * 64 + (((2 * ox)     ^ (m & 15)) << 2)];
            ulonglong2 vb = *(const ulonglong2*)&KVs[m * 64 + (((2 * ox + 1) ^ (m & 15)) << 2)];
            fma2(o[0], ee, va.x); fma2(o[1], ee, va.y);
            fma2(o[2], ee, vb.x); fma2(o[3], ee, vb.y);
        }
    }

    float inv = rinv[oy];
    float2 a0 = up2(o[0]), a1 = up2(o[1]), a2 = up2(o[2]), a3 = up2(o[3]);
    float4 w0 = make_float4(a0.x * inv, a0.y * inv, a1.x * inv, a1.y * inv);
    float4 w1 = make_float4(a2.x * inv, a2.y * inv, a3.x * inv, a3.y * inv);
    float* op = out + (size_t)(bh * SEQ + row0 + oy) * HDIM + ox * 8;
    *(float4*)op       = w0;
    *(float4*)(op + 4) = w1;
}

// ============================================================
// launch
// ============================================================
extern "C" void kernel_launch(void* const* d_in, const int* in_sizes, int n_in,
                              void* d_out, int out_size) {
    const float* x    = (const float*)d_in[0];   // [8,1024,768]
    const float* Wqkv = (const float*)d_in[1];   // [2304,768]
    const float* bqkv = (const float*)d_in[2];   // [2304]
    float* out = (float*)d_out;                  // [8,12,1024,64]

    const int attn_smem = (32 * SS_STRIDE + 32 * 64 + 64 * 64 + 32) * (int)sizeof(float); // 156800 B
    cudaFuncSetAttribute(attn_kernel, cudaFuncAttributeMaxDynamicSharedMemorySize, attn_smem);

    dim3 g1(THREE_E / 128, TOKENS / 128);  // 18 x 64
    qkv_gemm<<<g1, 256>>>(x, Wqkv, bqkv);

    attn_kernel<<<BATCH * HEADS * (SEQ / ROWS_PB), 256, attn_smem>>>(out);
}

// round 3
// speedup vs baseline: 2.1426x; 2.1426x over previous
#include <cuda_runtime.h>

#define EMBED   768
#define THREE_E 2304
#define HEADS   12
#define HDIM    64
#define SEQ     1024
#define BATCH   8
#define TOKENS  (BATCH*SEQ)

// QKV scratch: [8192 tokens][2304] fp32 (q | k | v, each 768 = 12 heads * 64)
__device__ float g_qkv[(size_t)TOKENS * THREE_E];

// ---------- packed f32x2 helpers (sm_100+) ----------
__device__ __forceinline__ unsigned long long pk2(float lo, float hi){
    unsigned long long r;
    asm("mov.b64 %0, {%1, %2};" : "=l"(r) : "f"(lo), "f"(hi));
    return r;
}
__device__ __forceinline__ unsigned long long dup2(float x){
    unsigned long long r;
    asm("mov.b64 %0, {%1, %1};" : "=l"(r) : "f"(x));
    return r;
}
__device__ __forceinline__ float2 up2(unsigned long long v){
    float2 r;
    asm("mov.b64 {%0, %1}, %2;" : "=f"(r.x), "=f"(r.y) : "l"(v));
    return r;
}
__device__ __forceinline__ void fma2(unsigned long long &d, unsigned long long a, unsigned long long b){
    asm("fma.rn.f32x2 %0, %1, %2, %0;" : "+l"(d) : "l"(a), "l"(b));
}

// ============================================================
// Kernel 1: QKV GEMM  C[8192,2304] = X[8192,768] * W[2304,768]^T + bias
// (unchanged — measured at ~42 TF/s, the f32x2 scalar ceiling)
// ============================================================
__global__ __launch_bounds__(256, 2)
void qkv_gemm(const float* __restrict__ X, const float* __restrict__ W,
              const float* __restrict__ bias){
    __shared__ float As[16][128];
    __shared__ float Bs[16][128];

    const int tid = threadIdx.x;
    const int bm = blockIdx.y * 128;
    const int bn = blockIdx.x * 128;
    const int tx = tid & 15;
    const int ty = tid >> 4;
    const int lr = tid >> 2;
    const int lc = (tid & 3) << 2;

    unsigned long long acc[8][4];
    #pragma unroll
    for (int i = 0; i < 8; i++)
        #pragma unroll
        for (int j = 0; j < 4; j++) acc[i][j] = 0ull;

    const float* Ap0 = X + (size_t)(bm + lr)      * EMBED + lc;
    const float* Ap1 = X + (size_t)(bm + lr + 64) * EMBED + lc;
    const float* Bp0 = W + (size_t)(bn + lr)      * EMBED + lc;
    const float* Bp1 = W + (size_t)(bn + lr + 64) * EMBED + lc;

    float4 pa0 = *(const float4*)Ap0;
    float4 pa1 = *(const float4*)Ap1;
    float4 pb0 = *(const float4*)Bp0;
    float4 pb1 = *(const float4*)Bp1;

    const int NKT = EMBED / 16;
    for (int kt = 0; kt < NKT; kt++){
        __syncthreads();
        {
            float a0[4] = {pa0.x, pa0.y, pa0.z, pa0.w};
            float a1[4] = {pa1.x, pa1.y, pa1.z, pa1.w};
            float b0[4] = {pb0.x, pb0.y, pb0.z, pb0.w};
            float b1[4] = {pb1.x, pb1.y, pb1.z, pb1.w};
            #pragma unroll
            for (int i = 0; i < 4; i++){
                As[lc + i][lr]      = a0[i];
                As[lc + i][lr + 64] = a1[i];
                Bs[lc + i][lr]      = b0[i];
                Bs[lc + i][lr + 64] = b1[i];
            }
        }
        __syncthreads();
        if (kt + 1 < NKT){
            pa0 = *(const float4*)(Ap0 + (kt + 1) * 16);
            pa1 = *(const float4*)(Ap1 + (kt + 1) * 16);
            pb0 = *(const float4*)(Bp0 + (kt + 1) * 16);
            pb1 = *(const float4*)(Bp1 + (kt + 1) * 16);
        }
        #pragma unroll
        for (int kk = 0; kk < 16; kk++){
            float4 a0 = *(const float4*)&As[kk][ty * 8];
            float4 a1 = *(const float4*)&As[kk][ty * 8 + 4];
            ulonglong2 b0 = *(const ulonglong2*)&Bs[kk][tx * 8];
            ulonglong2 b1 = *(const ulonglong2*)&Bs[kk][tx * 8 + 4];
            float av[8] = {a0.x, a0.y, a0.z, a0.w, a1.x, a1.y, a1.z, a1.w};
            #pragma unroll
            for (int i = 0; i < 8; i++){
                unsigned long long aa = dup2(av[i]);
                fma2(acc[i][0], aa, b0.x);
                fma2(acc[i][1], aa, b0.y);
                fma2(acc[i][2], aa, b1.x);
                fma2(acc[i][3], aa, b1.y);
            }
        }
    }

    float4 bs0 = *(const float4*)&bias[bn + tx * 8];
    float4 bs1 = *(const float4*)&bias[bn + tx * 8 + 4];
    #pragma unroll
    for (int i = 0; i < 8; i++){
        float2 c0 = up2(acc[i][0]), c1 = up2(acc[i][1]);
        float2 c2 = up2(acc[i][2]), c3 = up2(acc[i][3]);
        float4 o0 = make_float4(c0.x + bs0.x, c0.y + bs0.y, c1.x + bs0.z, c1.y + bs0.w);
        float4 o1 = make_float4(c2.x + bs1.x, c2.y + bs1.y, c3.x + bs1.z, c3.y + bs1.w);
        float* cp = g_qkv + (size_t)(bm + ty * 8 + i) * THREE_E + bn + tx * 8;
        *(float4*)cp       = o0;
        *(float4*)(cp + 4) = o1;
    }
}

// ============================================================
// Kernel 2: fused attention, FMA-bound layout.
// One CTA = (b, h, 32 Q rows). 8 warps.
// K/V tiles (64 seq x 64 d) stored d-major with XOR-chunk swizzle:
//   tile[d][m], phys 16B-chunk = (m>>2) ^ ((d>>2)&15)
// Pass1: warp = 8 rows x 32 cols (thread 2r x 4c), acc packs 2 adjacent
//        cols; Q scalar broadcast (dup2), K loads are f32x2 pairs.
// Pass2: warp = 8 rows x 32 cols (thread 4r x 2c), acc packs even/odd m;
//        e-weights load as 64-bit pairs straight from score strip. No dups.
// ============================================================
#define SSTR 1028   // 1024 + 4: rotates rows across bank groups
#define QSTR 68     // 64 + 4

__global__ __launch_bounds__(256, 1)
void attn_kernel(float* __restrict__ out){
    extern __shared__ float sm[];
    float* Ss   = sm;                    // 32 * 1028
    float* Qs   = Ss + 32 * SSTR;        // 32 * 68   (plain row-major)
    float* Ks   = Qs + 32 * QSTR;        // 64 * 64   (d-major, swizzled)
    float* Vs   = Ks + 64 * 64;          // 64 * 64   (d-major, swizzled)
    float* rinv = Vs + 64 * 64;          // 32

    const int tid  = threadIdx.x;
    const int warp = tid >> 5;
    const int lane = tid & 31;
    const int bh   = blockIdx.x >> 5;
    const int row0 = (blockIdx.x & 31) * 32;
    const int b = bh / HEADS;
    const int h = bh % HEADS;

    const float* qbase = g_qkv + (size_t)(b * SEQ) * THREE_E + h * HDIM;
    const float* kbase = qbase + EMBED;
    const float* vbase = qbase + 2 * EMBED;

    // loader coords (shared by K and V tile loads): 4 float4 per thread per tile
    const int ldc  = tid & 15;        // d-chunk 0..15 (d = ldc*4 + i)
    const int lrow = tid >> 4;        // base seq-row within tile (col_j = j*16 + lrow)

    // ---- load Q block 32x64 (plain layout; QSTR pad) ----
    #pragma unroll
    for (int it = 0; it < 2; it++){
        int idx = it * 256 + tid;
        int dc = idx & 15, r = idx >> 4;
        float4 v = *(const float4*)(qbase + (size_t)(row0 + r) * THREE_E + dc * 4);
        *(float4*)&Qs[r * QSTR + dc * 4] = v;
    }

    // =========== pass 1: S = floor(Q K^T / 8) ===========
    const int p1_r0    = (warp >> 1) * 8 + (lane >> 3) * 2;  // 2 rows
    const int p1_c0    = (warp & 1) * 32 + (lane & 7) * 4;   // 4 cols (in 64-col tile)
    const int p1_chunk = p1_c0 >> 2;                         // 0..15

    float4 kp[4];
    #pragma unroll
    for (int j = 0; j < 4; j++){
        int col = j * 16 + lrow;
        kp[j] = *(const float4*)(kbase + (size_t)col * THREE_E + ldc * 4);
    }

    #pragma unroll 1
    for (int kt = 0; kt < 16; kt++){
        // STS: transpose into d-major swizzled tile
        #pragma unroll
        for (int j = 0; j < 4; j++){
            int col  = j * 16 + lrow;
            int base = (ldc * 4) * 64 + (((col >> 2) ^ ldc) << 2) + (col & 3);
            Ks[base      ] = kp[j].x;
            Ks[base +  64] = kp[j].y;
            Ks[base + 128] = kp[j].z;
            Ks[base + 192] = kp[j].w;
        }
        __syncthreads();
        if (kt < 15){
            #pragma unroll
            for (int j = 0; j < 4; j++){
                int col = j * 16 + lrow;
                kp[j] = *(const float4*)(kbase + (size_t)((kt + 1) * 64 + col) * THREE_E + ldc * 4);
            }
        }

        unsigned long long a00 = 0ull, a01 = 0ull, a10 = 0ull, a11 = 0ull;
        #pragma unroll
        for (int dg = 0; dg < 16; dg++){
            float4 q0 = *(const float4*)&Qs[p1_r0 * QSTR + dg * 4];
            float4 q1 = *(const float4*)&Qs[(p1_r0 + 1) * QSTR + dg * 4];
            const float* kb = &Ks[(dg * 4) * 64 + ((p1_chunk ^ dg) << 2)];
            float q0v[4] = {q0.x, q0.y, q0.z, q0.w};
            float q1v[4] = {q1.x, q1.y, q1.z, q1.w};
            #pragma unroll
            for (int dd = 0; dd < 4; dd++){
                ulonglong2 kv = *(const ulonglong2*)(kb + dd * 64);
                unsigned long long aa0 = dup2(q0v[dd]);
                unsigned long long aa1 = dup2(q1v[dd]);
                fma2(a00, aa0, kv.x); fma2(a01, aa0, kv.y);
                fma2(a10, aa1, kv.x); fma2(a11, aa1, kv.y);
            }
        }
        float2 t0 = up2(a00), t1 = up2(a01), t2 = up2(a10), t3 = up2(a11);
        float4 w0 = make_float4(floorf(t0.x * 0.125f), floorf(t0.y * 0.125f),
                                floorf(t1.x * 0.125f), floorf(t1.y * 0.125f));
        float4 w1 = make_float4(floorf(t2.x * 0.125f), floorf(t2.y * 0.125f),
                                floorf(t3.x * 0.125f), floorf(t3.y * 0.125f));
        *(float4*)&Ss[p1_r0 * SSTR + kt * 64 + p1_c0]       = w0;
        *(float4*)&Ss[(p1_r0 + 1) * SSTR + kt * 64 + p1_c0] = w1;
        __syncthreads();
    }

    // ---- prefetch V tile 0 (hide gmem latency behind softmax) ----
    float4 vp[4];
    #pragma unroll
    for (int j = 0; j < 4; j++){
        int col = j * 16 + lrow;
        vp[j] = *(const float4*)(vbase + (size_t)col * THREE_E + ldc * 4);
    }

    // =========== softmax (exp in place, 1/sum -> rinv) ===========
    #pragma unroll
    for (int rr = 0; rr < 4; rr++){
        int r = warp * 4 + rr;
        float4* row4 = (float4*)&Ss[r * SSTR];
        float mx = -1e30f;
        #pragma unroll
        for (int i = 0; i < 8; i++){
            float4 v = row4[lane + i * 32];
            mx = fmaxf(mx, fmaxf(fmaxf(v.x, v.y), fmaxf(v.z, v.w)));
        }
        #pragma unroll
        for (int o = 16; o > 0; o >>= 1) mx = fmaxf(mx, __shfl_xor_sync(0xffffffffu, mx, o));
        float sum = 0.f;
        #pragma unroll
        for (int i = 0; i < 8; i++){
            float4 v = row4[lane + i * 32];
            v.x = __expf(v.x - mx); v.y = __expf(v.y - mx);
            v.z = __expf(v.z - mx); v.w = __expf(v.w - mx);
            sum += (v.x + v.y) + (v.z + v.w);
            row4[lane + i * 32] = v;
        }
        #pragma unroll
        for (int o = 16; o > 0; o >>= 1) sum += __shfl_xor_sync(0xffffffffu, sum, o);
        if (lane == 0) rinv[r] = 1.0f / sum;
    }

    // =========== pass 2: O = (E @ V) * rinv ===========
    const int p2_c0 = (warp & 1) * 32 + (lane & 15) * 2;     // 2 cols (d)
    const int p2_r0 = (warp >> 1) * 8 + (lane >> 4) * 4;     // 4 rows
    const int p2_key = p2_c0 >> 2;                            // same for c0, c0+1

    unsigned long long o00=0ull,o01=0ull,o10=0ull,o11=0ull,
                       o20=0ull,o21=0ull,o30=0ull,o31=0ull;

    #pragma unroll 1
    for (int kt = 0; kt < 16; kt++){
        #pragma unroll
        for (int j = 0; j < 4; j++){
            int col  = j * 16 + lrow;                  // seq index m within tile
            int base = (ldc * 4) * 64 + (((col >> 2) ^ ldc) << 2) + (col & 3);
            Vs[base      ] = vp[j].x;
            Vs[base +  64] = vp[j].y;
            Vs[base + 128] = vp[j].z;
            Vs[base + 192] = vp[j].w;
        }
        __syncthreads();   // also orders softmax stores on kt==0
        if (kt < 15){
            #pragma unroll
            for (int j = 0; j < 4; j++){
                int col = j * 16 + lrow;
                vp[j] = *(const float4*)(vbase + (size_t)((kt + 1) * 64 + col) * THREE_E + ldc * 4);
            }
        }

        const float* e0p = &Ss[(p2_r0    ) * SSTR + kt * 64];
        const float* e1p = &Ss[(p2_r0 + 1) * SSTR + kt * 64];
        const float* e2p = &Ss[(p2_r0 + 2) * SSTR + kt * 64];
        const float* e3p = &Ss[(p2_r0 + 3) * SSTR + kt * 64];
        const float* vb0 = &Vs[p2_c0 * 64];
        const float* vb1 = vb0 + 64;

        #pragma unroll
        for (int mg = 0; mg < 16; mg++){
            ulonglong2 e0 = *(const ulonglong2*)(e0p + mg * 4);
            ulonglong2 e1 = *(const ulonglong2*)(e1p + mg * 4);
            ulonglong2 e2 = *(const ulonglong2*)(e2p + mg * 4);
            ulonglong2 e3 = *(const ulonglong2*)(e3p + mg * 4);
            int off = (mg ^ p2_key) << 2;
            ulonglong2 v0 = *(const ulonglong2*)(vb0 + off);
            ulonglong2 v1 = *(const ulonglong2*)(vb1 + off);
            fma2(o00, e0.x, v0.x); fma2(o00, e0.y, v0.y);
            fma2(o01, e0.x, v1.x); fma2(o01, e0.y, v1.y);
            fma2(o10, e1.x, v0.x); fma2(o10, e1.y, v0.y);
            fma2(o11, e1.x, v1.x); fma2(o11, e1.y, v1.y);
            fma2(o20, e2.x, v0.x); fma2(o20, e2.y, v0.y);
            fma2(o21, e2.x, v1.x); fma2(o21, e2.y, v1.y);
            fma2(o30, e3.x, v0.x); fma2(o30, e3.y, v0.y);
            fma2(o31, e3.x, v1.x); fma2(o31, e3.y, v1.y);
        }
        __syncthreads();
    }

    // epilogue: horizontal add + normalize + store
    {
        float2 t;
        float i0 = rinv[p2_r0], i1 = rinv[p2_r0 + 1], i2 = rinv[p2_r0 + 2], i3 = rinv[p2_r0 + 3];
        float* op = out + (size_t)(bh * SEQ + row0 + p2_r0) * HDIM + p2_c0;
        float2 w;
        t = up2(o00); w.x = (t.x + t.y) * i0; t = up2(o01); w.y = (t.x + t.y) * i0;
        *(float2*)op = w;  op += HDIM;
        t = up2(o10); w.x = (t.x + t.y) * i1; t = up2(o11); w.y = (t.x + t.y) * i1;
        *(float2*)op = w;  op += HDIM;
        t = up2(o20); w.x = (t.x + t.y) * i2; t = up2(o21); w.y = (t.x + t.y) * i2;
        *(float2*)op = w;  op += HDIM;
        t = up2(o30); w.x = (t.x + t.y) * i3; t = up2(o31); w.y = (t.x + t.y) * i3;
        *(float2*)op = w;
    }
}

// ============================================================
// launch
// ============================================================
extern "C" void kernel_launch(void* const* d_in, const int* in_sizes, int n_in,
                              void* d_out, int out_size) {
    const float* x    = (const float*)d_in[0];   // [8,1024,768]
    const float* Wqkv = (const float*)d_in[1];   // [2304,768]
    const float* bqkv = (const float*)d_in[2];   // [2304]
    float* out = (float*)d_out;                  // [8,12,1024,64]

    const int attn_smem = (32 * SSTR + 32 * QSTR + 64 * 64 * 2 + 32) * (int)sizeof(float); // 173184 B
    cudaFuncSetAttribute(attn_kernel, cudaFuncAttributeMaxDynamicSharedMemorySize, attn_smem);

    dim3 g1(THREE_E / 128, TOKENS / 128);  // 18 x 64
    qkv_gemm<<<g1, 256>>>(x, Wqkv, bqkv);

    attn_kernel<<<BATCH * HEADS * (SEQ / 32), 256, attn_smem>>>(out);
}

// round 7
// speedup vs baseline: 2.5733x; 1.2010x over previous
#include <cuda_runtime.h>
#include <cstdint>

#define EMBED   768
#define THREE_E 2304
#define HEADS   12
#define HDIM    64
#define SEQ     1024
#define BATCH   8
#define TOKENS  (BATCH*SEQ)

// QKV scratch: [8192 tokens][2304] fp32 (q | k | v, each 768 = 12 heads * 64)
__device__ float g_qkv[(size_t)TOKENS * THREE_E];

// ---------- packed f32x2 helpers (sm_100+) ----------
__device__ __forceinline__ unsigned long long dup2(float x){
    unsigned long long r;
    asm("mov.b64 %0, {%1, %1};" : "=l"(r) : "f"(x));
    return r;
}
__device__ __forceinline__ float2 up2(unsigned long long v){
    float2 r;
    asm("mov.b64 {%0, %1}, %2;" : "=f"(r.x), "=f"(r.y) : "l"(v));
    return r;
}
__device__ __forceinline__ void fma2(unsigned long long &d, unsigned long long a, unsigned long long b){
    asm("fma.rn.f32x2 %0, %1, %2, %0;" : "+l"(d) : "l"(a), "l"(b));
}

// ---------- mma helpers ----------
__device__ __forceinline__ uint32_t smem_u32(const void* p){
    uint32_t a;
    asm("{ .reg .u64 t; cvta.to.shared.u64 t, %1; cvt.u32.u64 %0, t; }" : "=r"(a) : "l"(p));
    return a;
}
__device__ __forceinline__ float tf32r(float x){
    uint32_t u;
    asm("cvt.rna.tf32.f32 %0, %1;" : "=r"(u) : "f"(x));
    return __uint_as_float(u);
}
__device__ __forceinline__ void ldsm4(uint32_t r[4], uint32_t addr){
    asm volatile("ldmatrix.sync.aligned.m8n8.x4.shared.b16 {%0,%1,%2,%3}, [%4];"
                 : "=r"(r[0]), "=r"(r[1]), "=r"(r[2]), "=r"(r[3]) : "r"(addr));
}
__device__ __forceinline__ void mma_tf32(float c[4], const uint32_t a[4], const uint32_t b[2]){
    asm volatile(
        "mma.sync.aligned.m16n8k8.row.col.f32.tf32.tf32.f32 "
        "{%0,%1,%2,%3}, {%4,%5,%6,%7}, {%8,%9}, {%0,%1,%2,%3};"
        : "+f"(c[0]), "+f"(c[1]), "+f"(c[2]), "+f"(c[3])
        : "r"(a[0]), "r"(a[1]), "r"(a[2]), "r"(a[3]), "r"(b[0]), "r"(b[1]));
}

// ============================================================
// Kernel 1: QKV GEMM (R3 scalar f32x2 version — known good, exact fp32)
// ============================================================
__global__ __launch_bounds__(256, 2)
void qkv_gemm(const float* __restrict__ X, const float* __restrict__ W,
              const float* __restrict__ bias){
    __shared__ float As[16][128];
    __shared__ float Bs[16][128];

    const int tid = threadIdx.x;
    const int bm = blockIdx.y * 128;
    const int bn = blockIdx.x * 128;
    const int tx = tid & 15;
    const int ty = tid >> 4;
    const int lr = tid >> 2;
    const int lc = (tid & 3) << 2;

    unsigned long long acc[8][4];
    #pragma unroll
    for (int i = 0; i < 8; i++)
        #pragma unroll
        for (int j = 0; j < 4; j++) acc[i][j] = 0ull;

    const float* Ap0 = X + (size_t)(bm + lr)      * EMBED + lc;
    const float* Ap1 = X + (size_t)(bm + lr + 64) * EMBED + lc;
    const float* Bp0 = W + (size_t)(bn + lr)      * EMBED + lc;
    const float* Bp1 = W + (size_t)(bn + lr + 64) * EMBED + lc;

    float4 pa0 = *(const float4*)Ap0;
    float4 pa1 = *(const float4*)Ap1;
    float4 pb0 = *(const float4*)Bp0;
    float4 pb1 = *(const float4*)Bp1;

    const int NKT = EMBED / 16;
    for (int kt = 0; kt < NKT; kt++){
        __syncthreads();
        {
            float a0[4] = {pa0.x, pa0.y, pa0.z, pa0.w};
            float a1[4] = {pa1.x, pa1.y, pa1.z, pa1.w};
            float b0[4] = {pb0.x, pb0.y, pb0.z, pb0.w};
            float b1[4] = {pb1.x, pb1.y, pb1.z, pb1.w};
            #pragma unroll
            for (int i = 0; i < 4; i++){
                As[lc + i][lr]      = a0[i];
                As[lc + i][lr + 64] = a1[i];
                Bs[lc + i][lr]      = b0[i];
                Bs[lc + i][lr + 64] = b1[i];
            }
        }
        __syncthreads();
        if (kt + 1 < NKT){
            pa0 = *(const float4*)(Ap0 + (kt + 1) * 16);
            pa1 = *(const float4*)(Ap1 + (kt + 1) * 16);
            pb0 = *(const float4*)(Bp0 + (kt + 1) * 16);
            pb1 = *(const float4*)(Bp1 + (kt + 1) * 16);
        }
        #pragma unroll
        for (int kk = 0; kk < 16; kk++){
            float4 a0 = *(const float4*)&As[kk][ty * 8];
            float4 a1 = *(const float4*)&As[kk][ty * 8 + 4];
            ulonglong2 b0 = *(const ulonglong2*)&Bs[kk][tx * 8];
            ulonglong2 b1 = *(const ulonglong2*)&Bs[kk][tx * 8 + 4];
            float av[8] = {a0.x, a0.y, a0.z, a0.w, a1.x, a1.y, a1.z, a1.w};
            #pragma unroll
            for (int i = 0; i < 8; i++){
                unsigned long long aa = dup2(av[i]);
                fma2(acc[i][0], aa, b0.x);
                fma2(acc[i][1], aa, b0.y);
                fma2(acc[i][2], aa, b1.x);
                fma2(acc[i][3], aa, b1.y);
            }
        }
    }

    float4 bs0 = *(const float4*)&bias[bn + tx * 8];
    float4 bs1 = *(const float4*)&bias[bn + tx * 8 + 4];
    #pragma unroll
    for (int i = 0; i < 8; i++){
        float2 c0 = up2(acc[i][0]), c1 = up2(acc[i][1]);
        float2 c2 = up2(acc[i][2]), c3 = up2(acc[i][3]);
        float4 o0 = make_float4(c0.x + bs0.x, c0.y + bs0.y, c1.x + bs0.z, c1.y + bs0.w);
        float4 o1 = make_float4(c2.x + bs1.x, c2.y + bs1.y, c3.x + bs1.z, c3.y + bs1.w);
        float* cp = g_qkv + (size_t)(bm + ty * 8 + i) * THREE_E + bn + tx * 8;
        *(float4*)cp       = o0;
        *(float4*)(cp + 4) = o1;
    }
}

// ============================================================
// Kernel 2: fused attention.
// Pass 1 + softmax: identical to R3 (exact fp32 scores; softmax now
// stores tf32-rounded exp weights).
// Pass 2: tf32 mma.sync  C = E(32x1024) @ V(1024x64).
//   A-frags = E rows via ldmatrix.x4 directly from score strip.
//   B-frags = V from m-major Vs[64][68] via scalar LDS (<=2-way).
// ============================================================
#define SSTR 1028
#define QSTR 68
#define VSTR 68

__global__ __launch_bounds__(256, 1)
void attn_kernel(float* __restrict__ out){
    extern __shared__ float sm[];
    float* Ss   = sm;                    // 32 * 1028
    float* Qs   = Ss + 32 * SSTR;        // 32 * 68
    float* Ks   = Qs + 32 * QSTR;        // 64 * 64 (d-major swizzled, pass 1)
    float* Vs   = Ks + 64 * 64;          // 64 * 68 (m-major, pass 2)
    float* rinv = Vs + 64 * VSTR;        // 32

    const int tid  = threadIdx.x;
    const int warp = tid >> 5;
    const int lane = tid & 31;
    const int bh   = blockIdx.x >> 5;
    const int row0 = (blockIdx.x & 31) * 32;
    const int b = bh / HEADS;
    const int h = bh % HEADS;

    const float* qbase = g_qkv + (size_t)(b * SEQ) * THREE_E + h * HDIM;
    const float* kbase = qbase + EMBED;
    const float* vbase = qbase + 2 * EMBED;

    const int ldc  = tid & 15;
    const int lrow = tid >> 4;

    // ---- load Q block 32x64 ----
    #pragma unroll
    for (int it = 0; it < 2; it++){
        int idx = it * 256 + tid;
        int dc = idx & 15, r = idx >> 4;
        float4 v = *(const float4*)(qbase + (size_t)(row0 + r) * THREE_E + dc * 4);
        *(float4*)&Qs[r * QSTR + dc * 4] = v;
    }

    // =========== pass 1: S = floor(Q K^T / 8) (unchanged, exact fp32) ===========
    const int p1_r0    = (warp >> 1) * 8 + (lane >> 3) * 2;
    const int p1_c0    = (warp & 1) * 32 + (lane & 7) * 4;
    const int p1_chunk = p1_c0 >> 2;

    float4 kp[4];
    #pragma unroll
    for (int j = 0; j < 4; j++){
        int col = j * 16 + lrow;
        kp[j] = *(const float4*)(kbase + (size_t)col * THREE_E + ldc * 4);
    }

    #pragma unroll 1
    for (int kt = 0; kt < 16; kt++){
        #pragma unroll
        for (int j = 0; j < 4; j++){
            int col  = j * 16 + lrow;
            int base = (ldc * 4) * 64 + (((col >> 2) ^ ldc) << 2) + (col & 3);
            Ks[base      ] = kp[j].x;
            Ks[base +  64] = kp[j].y;
            Ks[base + 128] = kp[j].z;
            Ks[base + 192] = kp[j].w;
        }
        __syncthreads();
        if (kt < 15){
            #pragma unroll
            for (int j = 0; j < 4; j++){
                int col = j * 16 + lrow;
                kp[j] = *(const float4*)(kbase + (size_t)((kt + 1) * 64 + col) * THREE_E + ldc * 4);
            }
        }

        unsigned long long a00 = 0ull, a01 = 0ull, a10 = 0ull, a11 = 0ull;
        #pragma unroll
        for (int dg = 0; dg < 16; dg++){
            float4 q0 = *(const float4*)&Qs[p1_r0 * QSTR + dg * 4];
            float4 q1 = *(const float4*)&Qs[(p1_r0 + 1) * QSTR + dg * 4];
            const float* kb = &Ks[(dg * 4) * 64 + ((p1_chunk ^ dg) << 2)];
            float q0v[4] = {q0.x, q0.y, q0.z, q0.w};
            float q1v[4] = {q1.x, q1.y, q1.z, q1.w};
            #pragma unroll
            for (int dd = 0; dd < 4; dd++){
                ulonglong2 kv = *(const ulonglong2*)(kb + dd * 64);
                unsigned long long aa0 = dup2(q0v[dd]);
                unsigned long long aa1 = dup2(q1v[dd]);
                fma2(a00, aa0, kv.x); fma2(a01, aa0, kv.y);
                fma2(a10, aa1, kv.x); fma2(a11, aa1, kv.y);
            }
        }
        float2 t0 = up2(a00), t1 = up2(a01), t2 = up2(a10), t3 = up2(a11);
        float4 w0 = make_float4(floorf(t0.x * 0.125f), floorf(t0.y * 0.125f),
                                floorf(t1.x * 0.125f), floorf(t1.y * 0.125f));
        float4 w1 = make_float4(floorf(t2.x * 0.125f), floorf(t2.y * 0.125f),
                                floorf(t3.x * 0.125f), floorf(t3.y * 0.125f));
        *(float4*)&Ss[p1_r0 * SSTR + kt * 64 + p1_c0]       = w0;
        *(float4*)&Ss[(p1_r0 + 1) * SSTR + kt * 64 + p1_c0] = w1;
        __syncthreads();
    }

    // ---- prefetch V tile 0 (m-major loader: m = idx>>4, dchunk = idx&15) ----
    float4 vp[4];
    #pragma unroll
    for (int it = 0; it < 4; it++){
        int idx = it * 256 + tid;
        int m = idx >> 4, dc = idx & 15;
        vp[it] = *(const float4*)(vbase + (size_t)m * THREE_E + dc * 4);
    }

    // =========== softmax: exp stored tf32-rounded; 1/sum -> rinv ===========
    #pragma unroll
    for (int rr = 0; rr < 4; rr++){
        int r = warp * 4 + rr;
        float4* row4 = (float4*)&Ss[r * SSTR];
        float mx = -1e30f;
        #pragma unroll
        for (int i = 0; i < 8; i++){
            float4 v = row4[lane + i * 32];
            mx = fmaxf(mx, fmaxf(fmaxf(v.x, v.y), fmaxf(v.z, v.w)));
        }
        #pragma unroll
        for (int o = 16; o > 0; o >>= 1) mx = fmaxf(mx, __shfl_xor_sync(0xffffffffu, mx, o));
        float sum = 0.f;
        #pragma unroll
        for (int i = 0; i < 8; i++){
            float4 v = row4[lane + i * 32];
            v.x = tf32r(__expf(v.x - mx)); v.y = tf32r(__expf(v.y - mx));
            v.z = tf32r(__expf(v.z - mx)); v.w = tf32r(__expf(v.w - mx));
            sum += (v.x + v.y) + (v.z + v.w);
            row4[lane + i * 32] = v;
        }
        #pragma unroll
        for (int o = 16; o > 0; o >>= 1) sum += __shfl_xor_sync(0xffffffffu, sum, o);
        if (lane == 0) rinv[r] = 1.0f / sum;
    }

    // =========== pass 2: C = E @ V via tf32 mma ===========
    // warp -> (E m16-tile = warp&1, two n8 d-tiles at nt0 = (warp>>1)*2)
    const int mtile = warp & 1;
    const int nt0   = (warp >> 1) * 2;
    float C0[4] = {0.f,0.f,0.f,0.f}, C1[4] = {0.f,0.f,0.f,0.f};

    // E ldmatrix per-lane address base (row + col-half within k8)
    const uint32_t e_row  = (uint32_t)(mtile * 16 + (lane & 7) + ((lane >> 3) & 1) * 8);
    const uint32_t e_base = smem_u32(Ss) + e_row * (SSTR * 4) + (uint32_t)((lane >> 4) * 16);
    // V scalar-load coords: b0 = Vs[8ks + bm][nt*8 + bd], b1 = +4 rows
    const int bm_ = lane & 3;
    const int bd_ = lane >> 2;
    const float* vs_b0 = &Vs[bm_ * VSTR + nt0 * 8 + bd_];

    #pragma unroll 1
    for (int kt = 0; kt < 16; kt++){
        // store V tile (tf32-rounded, m-major, conflict-free float4 STS)
        #pragma unroll
        for (int it = 0; it < 4; it++){
            int idx = it * 256 + tid;
            int m = idx >> 4, dc = idx & 15;
            float4 v = vp[it];
            v.x = tf32r(v.x); v.y = tf32r(v.y); v.z = tf32r(v.z); v.w = tf32r(v.w);
            *(float4*)&Vs[m * VSTR + dc * 4] = v;
        }
        __syncthreads();   // also orders softmax stores on kt==0
        if (kt < 15){
            #pragma unroll
            for (int it = 0; it < 4; it++){
                int idx = it * 256 + tid;
                int m = idx >> 4, dc = idx & 15;
                vp[it] = *(const float4*)(vbase + (size_t)((kt + 1) * 64 + m) * THREE_E + dc * 4);
            }
        }

        const uint32_t e_kt = e_base + (uint32_t)(kt * 64 * 4);
        #pragma unroll
        for (int ks = 0; ks < 8; ks++){
            uint32_t ea[4];
            ldsm4(ea, e_kt + (uint32_t)(ks * 32));
            const float* vrow0 = vs_b0 + (8 * ks) * VSTR;       // k = 8ks + bm_
            const float* vrow1 = vrow0 + 4 * VSTR;              // k + 4
            uint32_t b0[2], b1[2];
            b0[0] = __float_as_uint(vrow0[0]);
            b0[1] = __float_as_uint(vrow1[0]);
            b1[0] = __float_as_uint(vrow0[8]);
            b1[1] = __float_as_uint(vrow1[8]);
            mma_tf32(C0, ea, b0);
            mma_tf32(C1, ea, b1);
        }
        __syncthreads();
    }

    // ---- epilogue: C frags -> out (scaled by rinv) ----
    {
        const int er0 = mtile * 16 + (lane >> 2);       // rows er0, er0+8
        const int d0  = nt0 * 8 + 2 * (lane & 3);
        float i0 = rinv[er0], i1 = rinv[er0 + 8];
        float* op0 = out + (size_t)(bh * SEQ + row0 + er0) * HDIM + d0;
        float* op1 = op0 + 8 * HDIM;
        *(float2*)op0       = make_float2(C0[0] * i0, C0[1] * i0);
        *(float2*)(op0 + 8) = make_float2(C1[0] * i0, C1[1] * i0);
        *(float2*)op1       = make_float2(C0[2] * i1, C0[3] * i1);
        *(float2*)(op1 + 8) = make_float2(C1[2] * i1, C1[3] * i1);
    }
}

// ============================================================
// launch
// ============================================================
extern "C" void kernel_launch(void* const* d_in, const int* in_sizes, int n_in,
                              void* d_out, int out_size) {
    const float* x    = (const float*)d_in[0];   // [8,1024,768]
    const float* Wqkv = (const float*)d_in[1];   // [2304,768]
    const float* bqkv = (const float*)d_in[2];   // [2304]
    float* out = (float*)d_out;                  // [8,12,1024,64]

    const int attn_smem = (32 * SSTR + 32 * QSTR + 64 * 64 + 64 * VSTR + 32) * (int)sizeof(float); // ~174 KB
    cudaFuncSetAttribute(attn_kernel, cudaFuncAttributeMaxDynamicSharedMemorySize, attn_smem);

    dim3 g1(THREE_E / 128, TOKENS / 128);
    qkv_gemm<<<g1, 256>>>(x, Wqkv, bqkv);

    attn_kernel<<<BATCH * HEADS * (SEQ / 32), 256, attn_smem>>>(out);
}

// round 8
// speedup vs baseline: 2.8439x; 1.1051x over previous
#include <cuda_runtime.h>
#include <cstdint>

#define EMBED   768
#define THREE_E 2304
#define HEADS   12
#define HDIM    64
#define SEQ     1024
#define BATCH   8
#define TOKENS  (BATCH*SEQ)

// QKV scratch: [8192 tokens][2304] fp32 (q | k | v, each 768 = 12 heads * 64)
__device__ float g_qkv[(size_t)TOKENS * THREE_E];

// ---------- packed f32x2 helpers (sm_100+) ----------
__device__ __forceinline__ unsigned long long dup2(float x){
    unsigned long long r;
    asm("mov.b64 %0, {%1, %1};" : "=l"(r) : "f"(x));
    return r;
}
__device__ __forceinline__ float2 up2(unsigned long long v){
    float2 r;
    asm("mov.b64 {%0, %1}, %2;" : "=f"(r.x), "=f"(r.y) : "l"(v));
    return r;
}
__device__ __forceinline__ void fma2(unsigned long long &d, unsigned long long a, unsigned long long b){
    asm("fma.rn.f32x2 %0, %1, %2, %0;" : "+l"(d) : "l"(a), "l"(b));
}

// ---------- mma helpers ----------
__device__ __forceinline__ uint32_t smem_u32(const void* p){
    uint32_t a;
    asm("{ .reg .u64 t; cvta.to.shared.u64 t, %1; cvt.u32.u64 %0, t; }" : "=r"(a) : "l"(p));
    return a;
}
__device__ __forceinline__ float tf32r(float x){
    uint32_t u;
    asm("cvt.rna.tf32.f32 %0, %1;" : "=r"(u) : "f"(x));
    return __uint_as_float(u);
}
__device__ __forceinline__ void ldsm4(uint32_t r[4], uint32_t addr){
    asm volatile("ldmatrix.sync.aligned.m8n8.x4.shared.b16 {%0,%1,%2,%3}, [%4];"
                 : "=r"(r[0]), "=r"(r[1]), "=r"(r[2]), "=r"(r[3]) : "r"(addr));
}
__device__ __forceinline__ void mma_tf32(float c[4], const uint32_t a[4], const uint32_t b[2]){
    asm volatile(
        "mma.sync.aligned.m16n8k8.row.col.f32.tf32.tf32.f32 "
        "{%0,%1,%2,%3}, {%4,%5,%6,%7}, {%8,%9}, {%0,%1,%2,%3};"
        : "+f"(c[0]), "+f"(c[1]), "+f"(c[2]), "+f"(c[3])
        : "r"(a[0]), "r"(a[1]), "r"(a[2]), "r"(a[3]), "r"(b[0]), "r"(b[1]));
}

// ============================================================
// Kernel 1: QKV GEMM (scalar f32x2 — known good, exact fp32)
// ============================================================
__global__ __launch_bounds__(256, 2)
void qkv_gemm(const float* __restrict__ X, const float* __restrict__ W,
              const float* __restrict__ bias){
    __shared__ float As[16][128];
    __shared__ float Bs[16][128];

    const int tid = threadIdx.x;
    const int bm = blockIdx.y * 128;
    const int bn = blockIdx.x * 128;
    const int tx = tid & 15;
    const int ty = tid >> 4;
    const int lr = tid >> 2;
    const int lc = (tid & 3) << 2;

    unsigned long long acc[8][4];
    #pragma unroll
    for (int i = 0; i < 8; i++)
        #pragma unroll
        for (int j = 0; j < 4; j++) acc[i][j] = 0ull;

    const float* Ap0 = X + (size_t)(bm + lr)      * EMBED + lc;
    const float* Ap1 = X + (size_t)(bm + lr + 64) * EMBED + lc;
    const float* Bp0 = W + (size_t)(bn + lr)      * EMBED + lc;
    const float* Bp1 = W + (size_t)(bn + lr + 64) * EMBED + lc;

    float4 pa0 = *(const float4*)Ap0;
    float4 pa1 = *(const float4*)Ap1;
    float4 pb0 = *(const float4*)Bp0;
    float4 pb1 = *(const float4*)Bp1;

    const int NKT = EMBED / 16;
    for (int kt = 0; kt < NKT; kt++){
        __syncthreads();
        {
            float a0[4] = {pa0.x, pa0.y, pa0.z, pa0.w};
            float a1[4] = {pa1.x, pa1.y, pa1.z, pa1.w};
            float b0[4] = {pb0.x, pb0.y, pb0.z, pb0.w};
            float b1[4] = {pb1.x, pb1.y, pb1.z, pb1.w};
            #pragma unroll
            for (int i = 0; i < 4; i++){
                As[lc + i][lr]      = a0[i];
                As[lc + i][lr + 64] = a1[i];
                Bs[lc + i][lr]      = b0[i];
                Bs[lc + i][lr + 64] = b1[i];
            }
        }
        __syncthreads();
        if (kt + 1 < NKT){
            pa0 = *(const float4*)(Ap0 + (kt + 1) * 16);
            pa1 = *(const float4*)(Ap1 + (kt + 1) * 16);
            pb0 = *(const float4*)(Bp0 + (kt + 1) * 16);
            pb1 = *(const float4*)(Bp1 + (kt + 1) * 16);
        }
        #pragma unroll
        for (int kk = 0; kk < 16; kk++){
            float4 a0 = *(const float4*)&As[kk][ty * 8];
            float4 a1 = *(const float4*)&As[kk][ty * 8 + 4];
            ulonglong2 b0 = *(const ulonglong2*)&Bs[kk][tx * 8];
            ulonglong2 b1 = *(const ulonglong2*)&Bs[kk][tx * 8 + 4];
            float av[8] = {a0.x, a0.y, a0.z, a0.w, a1.x, a1.y, a1.z, a1.w};
            #pragma unroll
            for (int i = 0; i < 8; i++){
                unsigned long long aa = dup2(av[i]);
                fma2(acc[i][0], aa, b0.x);
                fma2(acc[i][1], aa, b0.y);
                fma2(acc[i][2], aa, b1.x);
                fma2(acc[i][3], aa, b1.y);
            }
        }
    }

    float4 bs0 = *(const float4*)&bias[bn + tx * 8];
    float4 bs1 = *(const float4*)&bias[bn + tx * 8 + 4];
    #pragma unroll
    for (int i = 0; i < 8; i++){
        float2 c0 = up2(acc[i][0]), c1 = up2(acc[i][1]);
        float2 c2 = up2(acc[i][2]), c3 = up2(acc[i][3]);
        float4 o0 = make_float4(c0.x + bs0.x, c0.y + bs0.y, c1.x + bs0.z, c1.y + bs0.w);
        float4 o1 = make_float4(c2.x + bs1.x, c2.y + bs1.y, c3.x + bs1.z, c3.y + bs1.w);
        float* cp = g_qkv + (size_t)(bm + ty * 8 + i) * THREE_E + bn + tx * 8;
        *(float4*)cp       = o0;
        *(float4*)(cp + 4) = o1;
    }
}

// ============================================================
// Kernel 2: fused attention.
// Pass 1 (restructured): K tiles 256 seq x 64 d, m-major Ks[256][68]
//   (trivial conflict-free float4 loader). Thread tile 4r x 8c with
//   cols = lane + 32i (conflict-free K LDS: stride-68 rows). Exact
//   fp32 f32x2 accumulation over d-pairs; floor(s/8) unchanged.
// Softmax: unchanged (tf32-rounded exp weights).
// Pass 2: tf32 mma (unchanged from R7); Vs aliases Ks.
// ============================================================
#define SSTR 1028
#define QSTR 68
#define KSTR 68
#define VSTR 68

__global__ __launch_bounds__(256, 1)
void attn_kernel(float* __restrict__ out){
    extern __shared__ float sm[];
    float* Ss   = sm;                    // 32 * 1028
    float* Qs   = Ss + 32 * SSTR;        // 32 * 68
    float* Ks   = Qs + 32 * QSTR;        // 256 * 68 (m-major)
    float* rinv = Ks + 256 * KSTR;       // 32
    float* Vs   = Ks;                    // alias: pass 2 V tiles 64 x 68

    const int tid  = threadIdx.x;
    const int warp = tid >> 5;
    const int lane = tid & 31;
    const int bh   = blockIdx.x >> 5;
    const int row0 = (blockIdx.x & 31) * 32;
    const int b = bh / HEADS;
    const int h = bh % HEADS;

    const float* qbase = g_qkv + (size_t)(b * SEQ) * THREE_E + h * HDIM;
    const float* kbase = qbase + EMBED;
    const float* vbase = qbase + 2 * EMBED;

    // ---- load Q block 32x64 ----
    #pragma unroll
    for (int it = 0; it < 2; it++){
        int idx = it * 256 + tid;
        int dc = idx & 15, r = idx >> 4;
        float4 v = *(const float4*)(qbase + (size_t)(row0 + r) * THREE_E + dc * 4);
        *(float4*)&Qs[r * QSTR + dc * 4] = v;
    }
    __syncthreads();

    // =========== pass 1: S = floor(Q K^T / 8), exact fp32 ===========
    // warp rows r0..r0+3; thread cols lane + 32i (i<8) within 256-col tile
    const int r0 = warp * 4;

    #pragma unroll 1
    for (int kt = 0; kt < SEQ / 256; kt++){
        // load K tile 256 x 64 (m-major, conflict-free float4 STS)
        #pragma unroll
        for (int it = 0; it < 16; it++){
            int idx = it * 256 + tid;
            int m = idx >> 4, dc = idx & 15;
            float4 v = *(const float4*)(kbase + (size_t)(kt * 256 + m) * THREE_E + dc * 4);
            *(float4*)&Ks[m * KSTR + dc * 4] = v;
        }
        __syncthreads();

        unsigned long long acc[4][8];
        #pragma unroll
        for (int r = 0; r < 4; r++)
            #pragma unroll
            for (int i = 0; i < 8; i++) acc[r][i] = 0ull;

        #pragma unroll
        for (int dg = 0; dg < 16; dg++){
            ulonglong2 q[4];
            #pragma unroll
            for (int r = 0; r < 4; r++)
                q[r] = *(const ulonglong2*)&Qs[(r0 + r) * QSTR + dg * 4];
            #pragma unroll
            for (int i = 0; i < 8; i++){
                ulonglong2 kv = *(const ulonglong2*)&Ks[(lane + 32 * i) * KSTR + dg * 4];
                #pragma unroll
                for (int r = 0; r < 4; r++){
                    fma2(acc[r][i], q[r].x, kv.x);
                    fma2(acc[r][i], q[r].y, kv.y);
                }
            }
        }

        // horizontal add + floor + scalar store (conflict-free: col ≡ lane mod 32)
        #pragma unroll
        for (int r = 0; r < 4; r++){
            float* srow = &Ss[(r0 + r) * SSTR + kt * 256 + lane];
            #pragma unroll
            for (int i = 0; i < 8; i++){
                float2 t = up2(acc[r][i]);
                srow[32 * i] = floorf((t.x + t.y) * 0.125f);
            }
        }
        __syncthreads();
    }

    // ---- prefetch V tile 0 ----
    float4 vp[4];
    #pragma unroll
    for (int it = 0; it < 4; it++){
        int idx = it * 256 + tid;
        int m = idx >> 4, dc = idx & 15;
        vp[it] = *(const float4*)(vbase + (size_t)m * THREE_E + dc * 4);
    }

    // =========== softmax: exp stored tf32-rounded; 1/sum -> rinv ===========
    #pragma unroll
    for (int rr = 0; rr < 4; rr++){
        int r = warp * 4 + rr;
        float4* row4 = (float4*)&Ss[r * SSTR];
        float mx = -1e30f;
        #pragma unroll
        for (int i = 0; i < 8; i++){
            float4 v = row4[lane + i * 32];
            mx = fmaxf(mx, fmaxf(fmaxf(v.x, v.y), fmaxf(v.z, v.w)));
        }
        #pragma unroll
        for (int o = 16; o > 0; o >>= 1) mx = fmaxf(mx, __shfl_xor_sync(0xffffffffu, mx, o));
        float sum = 0.f;
        #pragma unroll
        for (int i = 0; i < 8; i++){
            float4 v = row4[lane + i * 32];
            v.x = tf32r(__expf(v.x - mx)); v.y = tf32r(__expf(v.y - mx));
            v.z = tf32r(__expf(v.z - mx)); v.w = tf32r(__expf(v.w - mx));
            sum += (v.x + v.y) + (v.z + v.w);
            row4[lane + i * 32] = v;
        }
        #pragma unroll
        for (int o = 16; o > 0; o >>= 1) sum += __shfl_xor_sync(0xffffffffu, sum, o);
        if (lane == 0) rinv[r] = 1.0f / sum;
    }

    // =========== pass 2: C = E @ V via tf32 mma (unchanged) ===========
    const int mtile = warp & 1;
    const int nt0   = (warp >> 1) * 2;
    float C0[4] = {0.f,0.f,0.f,0.f}, C1[4] = {0.f,0.f,0.f,0.f};

    const uint32_t e_row  = (uint32_t)(mtile * 16 + (lane & 7) + ((lane >> 3) & 1) * 8);
    const uint32_t e_base = smem_u32(Ss) + e_row * (SSTR * 4) + (uint32_t)((lane >> 4) * 16);
    const int bm_ = lane & 3;
    const int bd_ = lane >> 2;
    const float* vs_b0 = &Vs[bm_ * VSTR + nt0 * 8 + bd_];

    #pragma unroll 1
    for (int kt = 0; kt < 16; kt++){
        #pragma unroll
        for (int it = 0; it < 4; it++){
            int idx = it * 256 + tid;
            int m = idx >> 4, dc = idx & 15;
            float4 v = vp[it];
            v.x = tf32r(v.x); v.y = tf32r(v.y); v.z = tf32r(v.z); v.w = tf32r(v.w);
            *(float4*)&Vs[m * VSTR + dc * 4] = v;
        }
        __syncthreads();   // also orders softmax stores on kt==0
        if (kt < 15){
            #pragma unroll
            for (int it = 0; it < 4; it++){
                int idx = it * 256 + tid;
                int m = idx >> 4, dc = idx & 15;
                vp[it] = *(const float4*)(vbase + (size_t)((kt + 1) * 64 + m) * THREE_E + dc * 4);
            }
        }

        const uint32_t e_kt = e_base + (uint32_t)(kt * 64 * 4);
        #pragma unroll
        for (int ks = 0; ks < 8; ks++){
            uint32_t ea[4];
            ldsm4(ea, e_kt + (uint32_t)(ks * 32));
            const float* vrow0 = vs_b0 + (8 * ks) * VSTR;
            const float* vrow1 = vrow0 + 4 * VSTR;
            uint32_t b0[2], b1[2];
            b0[0] = __float_as_uint(vrow0[0]);
            b0[1] = __float_as_uint(vrow1[0]);
            b1[0] = __float_as_uint(vrow0[8]);
            b1[1] = __float_as_uint(vrow1[8]);
            mma_tf32(C0, ea, b0);
            mma_tf32(C1, ea, b1);
        }
        __syncthreads();
    }

    // ---- epilogue ----
    {
        const int er0 = mtile * 16 + (lane >> 2);
        const int d0  = nt0 * 8 + 2 * (lane & 3);
        float i0 = rinv[er0], i1 = rinv[er0 + 8];
        float* op0 = out + (size_t)(bh * SEQ + row0 + er0) * HDIM + d0;
        float* op1 = op0 + 8 * HDIM;
        *(float2*)op0       = make_float2(C0[0] * i0, C0[1] * i0);
        *(float2*)(op0 + 8) = make_float2(C1[0] * i0, C1[1] * i0);
        *(float2*)op1       = make_float2(C0[2] * i1, C0[3] * i1);
        *(float2*)(op1 + 8) = make_float2(C1[2] * i1, C1[3] * i1);
    }
}

// ============================================================
// launch
// ============================================================
extern "C" void kernel_launch(void* const* d_in, const int* in_sizes, int n_in,
                              void* d_out, int out_size) {
    const float* x    = (const float*)d_in[0];   // [8,1024,768]
    const float* Wqkv = (const float*)d_in[1];   // [2304,768]
    const float* bqkv = (const float*)d_in[2];   // [2304]
    float* out = (float*)d_out;                  // [8,12,1024,64]

    const int attn_smem = (32 * SSTR + 32 * QSTR + 256 * KSTR + 32) * (int)sizeof(float); // 210048 B
    cudaFuncSetAttribute(attn_kernel, cudaFuncAttributeMaxDynamicSharedMemorySize, attn_smem);

    dim3 g1(THREE_E / 128, TOKENS / 128);
    qkv_gemm<<<g1, 256>>>(x, Wqkv, bqkv);

    attn_kernel<<<BATCH * HEADS * (SEQ / 32), 256, attn_smem>>>(out);
}